// round 1
// baseline (speedup 1.0000x reference)
#include <cuda_runtime.h>

// Problem shape (fixed by the dataset): image [B,C,H,W] f32, flow [B,2,H,W] f32.
#define BB 8
#define CC 16
#define HH 512
#define WW 512
#define HWSZ (HH * WW)

__global__ __launch_bounds__(256) void warp_uv_kernel(
    const float* __restrict__ img,   // [B,C,H,W]
    const float* __restrict__ flo,   // [B,2,H,W]
    float* __restrict__ out)         // [B,C,H,W]
{
    const int pix = blockIdx.x * 256 + threadIdx.x;   // index within H*W
    const int b   = blockIdx.y;
    const int x   = pix & (WW - 1);
    const int y   = pix >> 9;                          // W == 512

    const float* flob = flo + (size_t)b * 2 * HWSZ;
    const float gx = (float)x + __ldg(flob + pix);
    const float gy = (float)y + __ldg(flob + HWSZ + pix);

    const float x0f = floorf(gx);
    const float y0f = floorf(gy);
    const float x1f = x0f + 1.0f;
    const float y1f = y0f + 1.0f;

    const float wx1 = gx - x0f, wx0 = 1.0f - wx1;
    const float wy1 = gy - y0f, wy0 = 1.0f - wy1;

    // Validity per corner, float-coordinate bounds like the reference.
    const float vx0 = (x0f >= 0.0f && x0f <= (float)(WW - 1)) ? 1.0f : 0.0f;
    const float vx1 = (x1f >= 0.0f && x1f <= (float)(WW - 1)) ? 1.0f : 0.0f;
    const float vy0 = (y0f >= 0.0f && y0f <= (float)(HH - 1)) ? 1.0f : 0.0f;
    const float vy1 = (y1f >= 0.0f && y1f <= (float)(HH - 1)) ? 1.0f : 0.0f;

    float w00 = wx0 * wy0 * (vx0 * vy0);   // corner (x0,y0)
    float w10 = wx1 * wy0 * (vx1 * vy0);   // corner (x1,y0)
    float w01 = wx0 * wy1 * (vx0 * vy1);   // corner (x0,y1)
    float w11 = wx1 * wy1 * (vx1 * vy1);   // corner (x1,y1)

    // mask = grid_sample(ones) with identical weights; threshold at 0.9999.
    const float mask = ((w00 + w10) + w01) + w11;
    const float m = (mask < 0.9999f) ? 0.0f : 1.0f;

    float* outb = out + (size_t)b * CC * HWSZ;

    if (m == 0.0f) {
        // All contributions zeroed: skip the 64 gathers, write zeros.
        #pragma unroll
        for (int c = 0; c < CC; ++c)
            outb[c * HWSZ + pix] = 0.0f;
        return;
    }

    // Clamped integer corner indices (weights already zero any invalid corner).
    const int xi0 = (int)fminf(fmaxf(x0f, 0.0f), (float)(WW - 1));
    const int xi1 = (int)fminf(fmaxf(x1f, 0.0f), (float)(WW - 1));
    const int yi0 = (int)fminf(fmaxf(y0f, 0.0f), (float)(HH - 1));
    const int yi1 = (int)fminf(fmaxf(y1f, 0.0f), (float)(HH - 1));

    const int i00 = yi0 * WW + xi0;
    const int i10 = yi0 * WW + xi1;
    const int i01 = yi1 * WW + xi0;
    const int i11 = yi1 * WW + xi1;

    const float* imgb = img + (size_t)b * CC * HWSZ;

    #pragma unroll
    for (int c = 0; c < CC; ++c) {
        const float* p = imgb + c * HWSZ;
        float v = w00 * __ldg(p + i00)
                + w10 * __ldg(p + i10)
                + w01 * __ldg(p + i01)
                + w11 * __ldg(p + i11);
        outb[c * HWSZ + pix] = v;
    }
}

extern "C" void kernel_launch(void* const* d_in, const int* in_sizes, int n_in,
                              void* d_out, int out_size)
{
    const float* img = (const float*)d_in[0];   // image [8,16,512,512]
    const float* flo = (const float*)d_in[1];   // UVgrid [8,2,512,512]
    float* out = (float*)d_out;

    dim3 grid(HWSZ / 256, BB);
    warp_uv_kernel<<<grid, 256>>>(img, flo, out);
}

// round 2
// speedup vs baseline: 1.2218x; 1.2218x over previous
#include <cuda_runtime.h>

// image [8,16,512,512] f32, flow [8,2,512,512] f32, out [8,16,512,512] f32
#define BB 8
#define CC 16
#define HH 512
#define WW 512
#define HWSZ (HH * WW)

#define TILE 64            // output tile edge
#define RAD  20            // halo radius (covers |flow| <= ~20px in-tile)
#define TW   (TILE + 2*RAD + 1)   // 105
#define THT  (TILE + 2*RAD + 1)   // 105
#define NT   1024
#define PPT  4             // pixels per thread = TILE*TILE/NT

#define MT_ZERO 0x80000000u
#define MT_GLB  0x40000000u

__global__ __launch_bounds__(NT, 1) void warp_tile_kernel(
    const float* __restrict__ img,
    const float* __restrict__ flo,
    float* __restrict__ out)
{
    __shared__ float tile[TW * THT];   // 44.1 KB

    const int tx0 = blockIdx.x * TILE;
    const int ty0 = blockIdx.y * TILE;
    const int b   = blockIdx.z;
    const int TX0 = tx0 - RAD;
    const int TY0 = ty0 - RAD;

    const int tid = threadIdx.x;
    const int lx  = tid & (TILE - 1);   // 0..63
    const int lyb = tid >> 6;           // 0..15

    const float* flob = flo + (size_t)b * 2 * HWSZ;
    const float* imgb = img + (size_t)b * CC * HWSZ;
    float*       outb = out + (size_t)b * CC * HWSZ;

    unsigned meta[PPT];
    float A0[PPT], A1[PPT], B0[PPT], B1[PPT];  // wx0*vx0, wx1*vx1, wy0*vy0, wy1*vy1

    #pragma unroll
    for (int k = 0; k < PPT; ++k) {
        const int ly  = lyb + k * 16;
        const int x   = tx0 + lx;
        const int y   = ty0 + ly;
        const int pix = y * WW + x;

        const float gx = (float)x + __ldg(flob + pix);
        const float gy = (float)y + __ldg(flob + HWSZ + pix);

        const float x0f = floorf(gx);
        const float y0f = floorf(gy);
        const float x1f = x0f + 1.0f;
        const float y1f = y0f + 1.0f;

        const float wx1 = gx - x0f, wx0 = 1.0f - wx1;
        const float wy1 = gy - y0f, wy0 = 1.0f - wy1;

        const float vx0 = (x0f >= 0.0f && x0f <= 511.0f) ? 1.0f : 0.0f;
        const float vx1 = (x1f >= 0.0f && x1f <= 511.0f) ? 1.0f : 0.0f;
        const float vy0 = (y0f >= 0.0f && y0f <= 511.0f) ? 1.0f : 0.0f;
        const float vy1 = (y1f >= 0.0f && y1f <= 511.0f) ? 1.0f : 0.0f;

        // a*b == (wx*wy)*(vx*vy) bit-exactly (multiplying by 0.0/1.0 is exact)
        const float a0 = wx0 * vx0, a1 = wx1 * vx1;
        const float b0 = wy0 * vy0, b1 = wy1 * vy1;
        A0[k] = a0; A1[k] = a1; B0[k] = b0; B1[k] = b1;

        // mask in the reference's exact summation order
        const float w00 = a0 * b0, w10 = a1 * b0, w01 = a0 * b1, w11 = a1 * b1;
        const float mask = ((w00 + w10) + w01) + w11;

        unsigned mt;
        if (mask < 0.9999f) {
            mt = MT_ZERO;
        } else {
            // mask passed -> at least partial validity -> x0,y0 in [-1, 511]
            const int x0 = (int)x0f;
            const int y0 = (int)y0f;
            const bool insm = (x0 >= TX0) && (x0 <= TX0 + TW - 2) &&
                              (y0 >= TY0) && (y0 <= TY0 + THT - 2);
            if (insm)
                mt = (unsigned)((y0 - TY0) * TW + (x0 - TX0));
            else
                mt = MT_GLB | ((unsigned)(y0 + 1) << 10) | (unsigned)(x0 + 1);
        }
        meta[k] = mt;
    }

    for (int c = 0; c < CC; ++c) {
        const float* ic = imgb + c * HWSZ;

        __syncthreads();   // previous channel's gathers done before overwrite
        #pragma unroll 4
        for (int i = tid; i < TW * THT; i += NT) {
            const int row = i / TW;
            const int col = i - row * TW;
            const int gyi = TY0 + row;
            const int gxi = TX0 + col;
            float v = 0.0f;
            if ((unsigned)gyi < (unsigned)HH && (unsigned)gxi < (unsigned)WW)
                v = __ldg(ic + gyi * WW + gxi);
            tile[i] = v;
        }
        __syncthreads();

        float* oc = outb + c * HWSZ;
        #pragma unroll
        for (int k = 0; k < PPT; ++k) {
            const int ly   = lyb + k * 16;
            const int opix = (ty0 + ly) * WW + (tx0 + lx);
            const unsigned mt = meta[k];

            float v;
            if (mt & MT_ZERO) {
                v = 0.0f;
            } else if (mt & MT_GLB) {
                const int x0 = (int)(mt & 0x3FFu) - 1;
                const int y0 = (int)((mt >> 10) & 0x3FFu) - 1;
                const int xc0 = max(x0, 0), xc1 = min(x0 + 1, WW - 1);
                const int yc0 = max(y0, 0), yc1 = min(y0 + 1, HH - 1);
                v = (A0[k] * B0[k]) * __ldg(ic + yc0 * WW + xc0)
                  + (A1[k] * B0[k]) * __ldg(ic + yc0 * WW + xc1)
                  + (A0[k] * B1[k]) * __ldg(ic + yc1 * WW + xc0)
                  + (A1[k] * B1[k]) * __ldg(ic + yc1 * WW + xc1);
            } else {
                const int s = (int)mt;
                const float p00 = tile[s];
                const float p10 = tile[s + 1];
                const float p01 = tile[s + TW];
                const float p11 = tile[s + TW + 1];
                v = (A0[k] * B0[k]) * p00 + (A1[k] * B0[k]) * p10
                  + (A0[k] * B1[k]) * p01 + (A1[k] * B1[k]) * p11;
            }
            oc[opix] = v;
        }
    }
}

extern "C" void kernel_launch(void* const* d_in, const int* in_sizes, int n_in,
                              void* d_out, int out_size)
{
    const float* img = (const float*)d_in[0];
    const float* flo = (const float*)d_in[1];
    float* out = (float*)d_out;

    dim3 grid(WW / TILE, HH / TILE, BB);   // 8 x 8 x 8 = 512 CTAs
    warp_tile_kernel<<<grid, NT>>>(img, flo, out);
}

// round 3
// speedup vs baseline: 1.7802x; 1.4570x over previous
#include <cuda_runtime.h>

// image [8,16,512,512] f32, flow [8,2,512,512] f32, out [8,16,512,512] f32
#define BB 8
#define CC 16
#define HH 512
#define WW 512
#define HWSZ (HH * WW)

#define TILE 64                      // output tile edge
#define RAD  20                      // halo radius
#define TW   (TILE + 2*RAD + 1)      // 105
#define NPIX (TW * TW)               // 11025 halo pixels
#define NT   512
#define PPT  8                       // output pixels per thread
#define NG   8                       // channel groups of 2
#define SMEM_BYTES (NPIX * 8)        // float2 tile = 88200 B

#define MT_ZERO 0x80000000u
#define MT_GLB  0x40000000u

__global__ __launch_bounds__(NT, 2) void warp_tile2_kernel(
    const float* __restrict__ img,
    const float* __restrict__ flo,
    float* __restrict__ out)
{
    extern __shared__ float2 tile[];   // [TW*TW] channel-pair interleaved

    const int tx0 = blockIdx.x * TILE;
    const int ty0 = blockIdx.y * TILE;
    const int b   = blockIdx.z;
    const int TX0 = tx0 - RAD;
    const int TY0 = ty0 - RAD;

    const int tid = threadIdx.x;
    const int lx  = tid & (TILE - 1);  // 0..63
    const int lyb = tid >> 6;          // 0..7

    const float* flob = flo + (size_t)b * 2 * HWSZ;
    const float* imgb = img + (size_t)b * CC * HWSZ;
    float*       outb = out + (size_t)b * CC * HWSZ;

    unsigned meta[PPT];
    float W00[PPT], W10[PPT], W01[PPT], W11[PPT];

    #pragma unroll
    for (int k = 0; k < PPT; ++k) {
        const int ly  = lyb + k * 8;
        const int x   = tx0 + lx;
        const int y   = ty0 + ly;
        const int pix = y * WW + x;

        const float gx = (float)x + __ldg(flob + pix);
        const float gy = (float)y + __ldg(flob + HWSZ + pix);

        const float x0f = floorf(gx);
        const float y0f = floorf(gy);
        const float x1f = x0f + 1.0f;
        const float y1f = y0f + 1.0f;

        const float wx1 = gx - x0f, wx0 = 1.0f - wx1;
        const float wy1 = gy - y0f, wy0 = 1.0f - wy1;

        const float vx0 = (x0f >= 0.0f && x0f <= 511.0f) ? 1.0f : 0.0f;
        const float vx1 = (x1f >= 0.0f && x1f <= 511.0f) ? 1.0f : 0.0f;
        const float vy0 = (y0f >= 0.0f && y0f <= 511.0f) ? 1.0f : 0.0f;
        const float vy1 = (y1f >= 0.0f && y1f <= 511.0f) ? 1.0f : 0.0f;

        const float a0 = wx0 * vx0, a1 = wx1 * vx1;
        const float b0 = wy0 * vy0, b1 = wy1 * vy1;

        const float w00 = a0 * b0, w10 = a1 * b0, w01 = a0 * b1, w11 = a1 * b1;
        W00[k] = w00; W10[k] = w10; W01[k] = w01; W11[k] = w11;

        const float mask = ((w00 + w10) + w01) + w11;

        unsigned mt;
        if (mask < 0.9999f) {
            mt = MT_ZERO;
        } else {
            const int x0 = (int)x0f;
            const int y0 = (int)y0f;
            const bool insm = (x0 >= TX0) && (x0 <= TX0 + TW - 2) &&
                              (y0 >= TY0) && (y0 <= TY0 + TW - 2);
            if (insm)
                mt = (unsigned)((y0 - TY0) * TW + (x0 - TX0));
            else
                mt = MT_GLB | ((unsigned)(y0 + 1) << 10) | (unsigned)(x0 + 1);
        }
        meta[k] = mt;
    }

    for (int g = 0; g < NG; ++g) {
        const float* ic = imgb + (size_t)(2 * g) * HWSZ;   // channel 2g plane

        __syncthreads();   // previous group's gathers done before overwrite
        #pragma unroll
        for (int j = 0; j < (NPIX + NT - 1) / NT; ++j) {
            const int i = tid + j * NT;
            if (i < NPIX) {
                const int row = i / TW;
                const int col = i - row * TW;
                const int gyi = TY0 + row;
                const int gxi = TX0 + col;
                float v0 = 0.0f, v1 = 0.0f;
                if ((unsigned)gyi < (unsigned)HH && (unsigned)gxi < (unsigned)WW) {
                    const int off = gyi * WW + gxi;
                    v0 = __ldg(ic + off);
                    v1 = __ldg(ic + HWSZ + off);
                }
                tile[i] = make_float2(v0, v1);
            }
        }
        __syncthreads();

        float* oc = outb + (size_t)(2 * g) * HWSZ;
        #pragma unroll
        for (int k = 0; k < PPT; ++k) {
            const int ly   = lyb + k * 8;
            const int opix = (ty0 + ly) * WW + (tx0 + lx);
            const unsigned mt = meta[k];

            float vx, vy;
            if (mt & MT_ZERO) {
                vx = 0.0f; vy = 0.0f;
            } else if (mt & MT_GLB) {
                const int x0 = (int)(mt & 0x3FFu) - 1;
                const int y0 = (int)((mt >> 10) & 0x3FFu) - 1;
                const int xc0 = max(x0, 0), xc1 = min(x0 + 1, WW - 1);
                const int yc0 = max(y0, 0), yc1 = min(y0 + 1, HH - 1);
                const int i00 = yc0 * WW + xc0, i10 = yc0 * WW + xc1;
                const int i01 = yc1 * WW + xc0, i11 = yc1 * WW + xc1;
                vx = W00[k] * __ldg(ic + i00) + W10[k] * __ldg(ic + i10)
                   + W01[k] * __ldg(ic + i01) + W11[k] * __ldg(ic + i11);
                vy = W00[k] * __ldg(ic + HWSZ + i00) + W10[k] * __ldg(ic + HWSZ + i10)
                   + W01[k] * __ldg(ic + HWSZ + i01) + W11[k] * __ldg(ic + HWSZ + i11);
            } else {
                const int s = (int)mt;
                const float2 p00 = tile[s];
                const float2 p10 = tile[s + 1];
                const float2 p01 = tile[s + TW];
                const float2 p11 = tile[s + TW + 1];
                vx = W00[k] * p00.x + W10[k] * p10.x + W01[k] * p01.x + W11[k] * p11.x;
                vy = W00[k] * p00.y + W10[k] * p10.y + W01[k] * p01.y + W11[k] * p11.y;
            }
            oc[opix]        = vx;
            oc[HWSZ + opix] = vy;
        }
    }
}

extern "C" void kernel_launch(void* const* d_in, const int* in_sizes, int n_in,
                              void* d_out, int out_size)
{
    const float* img = (const float*)d_in[0];
    const float* flo = (const float*)d_in[1];
    float* out = (float*)d_out;

    cudaFuncSetAttribute(warp_tile2_kernel,
                         cudaFuncAttributeMaxDynamicSharedMemorySize, SMEM_BYTES);

    dim3 grid(WW / TILE, HH / TILE, BB);   // 8 x 8 x 8 = 512 CTAs
    warp_tile2_kernel<<<grid, NT, SMEM_BYTES>>>(img, flo, out);
}

// round 4
// speedup vs baseline: 2.5293x; 1.4208x over previous
#include <cuda_runtime.h>

// image [8,16,512,512] f32, flow [8,2,512,512] f32, out [8,16,512,512] f32
#define BB 8
#define CC 16
#define HH 512
#define WW 512
#define HWSZ (HH * WW)

// 128 MB NHWC scratch ([B,H,W,C]) — static device allocation (allowed).
__device__ float g_timg[(size_t)BB * HWSZ * CC];

// ---------------------------------------------------------------------------
// Kernel 1: NCHW -> NHWC transpose. Coalesced reads per channel plane,
// 4x STG.128 contiguous writes per pixel.
// ---------------------------------------------------------------------------
__global__ __launch_bounds__(256) void transpose_kernel(
    const float* __restrict__ img)
{
    const int pix = blockIdx.x * 256 + threadIdx.x;
    const int b   = blockIdx.z;

    const float* src = img + (size_t)b * CC * HWSZ + pix;

    float v[CC];
    #pragma unroll
    for (int c = 0; c < CC; ++c)
        v[c] = __ldg(src + (size_t)c * HWSZ);

    float4* dst = (float4*)g_timg + ((size_t)b * HWSZ + pix) * 4;
    dst[0] = make_float4(v[0],  v[1],  v[2],  v[3]);
    dst[1] = make_float4(v[4],  v[5],  v[6],  v[7]);
    dst[2] = make_float4(v[8],  v[9],  v[10], v[11]);
    dst[3] = make_float4(v[12], v[13], v[14], v[15]);
}

// ---------------------------------------------------------------------------
// Kernel 2: warp gather from NHWC. 4 lanes per output pixel; lane j owns
// channel chunk [4j..4j+3]. Each corner fetch is one LDG.128 whose 4-lane
// group covers a contiguous 64B (always within one 128B line).
// ---------------------------------------------------------------------------
__global__ __launch_bounds__(256) void gather_kernel(
    const float* __restrict__ flo,
    float* __restrict__ out)
{
    const int j   = threadIdx.x & 3;                       // channel chunk
    const int pix = blockIdx.x * 64 + (threadIdx.x >> 2);  // pixel in H*W
    const int b   = blockIdx.z;
    const int x   = pix & (WW - 1);
    const int y   = pix >> 9;

    const float* flob = flo + (size_t)b * 2 * HWSZ;
    const float gx = (float)x + __ldg(flob + pix);
    const float gy = (float)y + __ldg(flob + HWSZ + pix);

    const float x0f = floorf(gx);
    const float y0f = floorf(gy);
    const float x1f = x0f + 1.0f;
    const float y1f = y0f + 1.0f;

    const float wx1 = gx - x0f, wx0 = 1.0f - wx1;
    const float wy1 = gy - y0f, wy0 = 1.0f - wy1;

    const float vx0 = (x0f >= 0.0f && x0f <= 511.0f) ? 1.0f : 0.0f;
    const float vx1 = (x1f >= 0.0f && x1f <= 511.0f) ? 1.0f : 0.0f;
    const float vy0 = (y0f >= 0.0f && y0f <= 511.0f) ? 1.0f : 0.0f;
    const float vy1 = (y1f >= 0.0f && y1f <= 511.0f) ? 1.0f : 0.0f;

    const float a0 = wx0 * vx0, a1 = wx1 * vx1;
    const float b0 = wy0 * vy0, b1 = wy1 * vy1;

    const float w00 = a0 * b0, w10 = a1 * b0, w01 = a0 * b1, w11 = a1 * b1;
    const float mask = ((w00 + w10) + w01) + w11;   // reference's exact order

    float* oc = out + (size_t)b * CC * HWSZ + pix;

    if (mask < 0.9999f) {
        #pragma unroll
        for (int k = 0; k < 4; ++k)
            oc[(size_t)(4 * j + k) * HWSZ] = 0.0f;
        return;
    }

    // Clamped corner indices (weights already zero any invalid corner).
    const int xi0 = max((int)x0f, 0), xi1 = min((int)x0f + 1, WW - 1);
    const int yi0 = max((int)y0f, 0), yi1 = min((int)y0f + 1, HH - 1);

    const float4* base = (const float4*)g_timg + (size_t)b * HWSZ * 4;

    const float4 v00 = __ldg(base + (yi0 * WW + xi0) * 4 + j);
    const float4 v10 = __ldg(base + (yi0 * WW + xi1) * 4 + j);
    const float4 v01 = __ldg(base + (yi1 * WW + xi0) * 4 + j);
    const float4 v11 = __ldg(base + (yi1 * WW + xi1) * 4 + j);

    float4 r;
    r.x = w00 * v00.x + w10 * v10.x + w01 * v01.x + w11 * v11.x;
    r.y = w00 * v00.y + w10 * v10.y + w01 * v01.y + w11 * v11.y;
    r.z = w00 * v00.z + w10 * v10.z + w01 * v01.z + w11 * v11.z;
    r.w = w00 * v00.w + w10 * v10.w + w01 * v01.w + w11 * v11.w;

    oc[(size_t)(4 * j + 0) * HWSZ] = r.x;
    oc[(size_t)(4 * j + 1) * HWSZ] = r.y;
    oc[(size_t)(4 * j + 2) * HWSZ] = r.z;
    oc[(size_t)(4 * j + 3) * HWSZ] = r.w;
}

extern "C" void kernel_launch(void* const* d_in, const int* in_sizes, int n_in,
                              void* d_out, int out_size)
{
    const float* img = (const float*)d_in[0];
    const float* flo = (const float*)d_in[1];
    float* out = (float*)d_out;

    dim3 gridT(HWSZ / 256, 1, BB);
    transpose_kernel<<<gridT, 256>>>(img);

    dim3 gridG(HWSZ / 64, 1, BB);   // 4 lanes per pixel, 64 pixels per block
    gather_kernel<<<gridG, 256>>>(flo, out);
}